// round 14
// baseline (speedup 1.0000x reference)
#include <cuda_runtime.h>
#include <cuda_bf16.h>
#include <math.h>
#include <cstdint>

#define NB 2
#define NT 4096
#define NC 1024
#define NH 8
#define ND 128
#define NW 512

// ---------------- scratch (__device__ globals; no allocs allowed) ----------
__device__ float g_qkv[NB * NT * 3 * NC];   // [B*T, 3C]
__device__ float g_invf[64];

__device__ __align__(256) __nv_bfloat16 g_xh[NB * NT * NC], g_xl[NB * NT * NC];
__device__ __align__(256) __nv_bfloat16 g_wqh[3 * NC * NC], g_wql[3 * NC * NC];
__device__ __align__(256) __nv_bfloat16 g_woh[NC * NC],     g_wol[NC * NC];
__device__ __align__(256) __nv_bfloat16 g_ah[NB * NT * NC], g_al[NB * NT * NC];

__device__ __align__(256) __nv_bfloat16 g_qh[NB * NH * NT * ND], g_ql[NB * NH * NT * ND];
__device__ __align__(256) __nv_bfloat16 g_kh[NB * NH * NT * ND], g_kl[NB * NH * NT * ND];
__device__ __align__(256) __nv_bfloat16 g_vth[NB * NH * ND * NT], g_vtl[NB * NH * ND * NT]; // [bh][d][t]

// ---------------- helpers ---------------------------------------------------
__device__ __forceinline__ uint32_t smem_u32(const void* p) {
    uint32_t a;
    asm("{ .reg .u64 t; cvta.to.shared.u64 t, %1; cvt.u32.u64 %0, t; }" : "=r"(a) : "l"(p));
    return a;
}
// 64B-row packed tile swizzle (two 64B gmem rows per 128B smem row)
__device__ __forceinline__ uint32_t toff(int r, int cu) {
    uint32_t o = ((uint32_t)(r >> 1) << 7) + ((uint32_t)(r & 1) << 6) + ((uint32_t)cu << 4);
    return o ^ ((o >> 3) & 0x70);
}
// 256B-row tile swizzle (u in 0..15) and 128B-row tile swizzle (u in 0..7)
__device__ __forceinline__ uint32_t q_off(int r, int u)  { return (uint32_t)(r * 256 + ((u ^ (r & 7)) << 4)); }
__device__ __forceinline__ uint32_t vt_off(int r, int u) { return (uint32_t)(r * 128 + ((u ^ (r & 7)) << 4)); }

#define LDSM4(r0, r1, r2, r3, ad) \
    asm volatile("ldmatrix.sync.aligned.m8n8.x4.shared.b16 {%0,%1,%2,%3}, [%4];" \
                 : "=r"(r0), "=r"(r1), "=r"(r2), "=r"(r3) : "r"(ad))
#define LDSM4A(a, ad) LDSM4((a)[0], (a)[1], (a)[2], (a)[3], ad)

#define MMA16816(d, a0, a1, a2, a3, b0, b1) \
    asm volatile("mma.sync.aligned.m16n8k16.row.col.f32.bf16.bf16.f32 " \
                 "{%0,%1,%2,%3},{%4,%5,%6,%7},{%8,%9},{%0,%1,%2,%3};" \
                 : "+f"((d)[0]), "+f"((d)[1]), "+f"((d)[2]), "+f"((d)[3]) \
                 : "r"(a0), "r"(a1), "r"(a2), "r"(a3), "r"(b0), "r"(b1))

#define CP_ASYNC16(sa, ga) \
    asm volatile("cp.async.cg.shared.global [%0], [%1], 16;" :: "r"(sa), "l"(ga))
#define CP_COMMIT() asm volatile("cp.async.commit_group;" ::: "memory")
#define CP_WAIT0()  asm volatile("cp.async.wait_group 0;" ::: "memory")
#define CP_WAIT1()  asm volatile("cp.async.wait_group 1;" ::: "memory")

__device__ __forceinline__ void packsplit2(float a, float b, uint32_t& hi, uint32_t& lo) {
    __nv_bfloat16 ha = __float2bfloat16(a), hb = __float2bfloat16(b);
    __nv_bfloat162 hp; hp.x = ha; hp.y = hb;
    __nv_bfloat162 lp;
    lp.x = __float2bfloat16(a - __bfloat162float(ha));
    lp.y = __float2bfloat16(b - __bfloat162float(hb));
    hi = *reinterpret_cast<uint32_t*>(&hp);
    lo = *reinterpret_cast<uint32_t*>(&lp);
}
__device__ __forceinline__ void split_store2(__nv_bfloat16* H, __nv_bfloat16* L,
                                             size_t idx, float a, float b) {
    uint32_t hi, lo;
    packsplit2(a, b, hi, lo);
    *reinterpret_cast<uint32_t*>(&H[idx]) = hi;
    *reinterpret_cast<uint32_t*>(&L[idx]) = lo;
}

// ---------------------------------------------------------------------------
// fp32 -> (hi, lo) bf16 split
// ---------------------------------------------------------------------------
__global__ void conv_split(const float* __restrict__ s, __nv_bfloat16* __restrict__ h,
                           __nv_bfloat16* __restrict__ l, int n)
{
    int i = (blockIdx.x * 256 + threadIdx.x) * 4;
    if (i >= n) return;
    float4 v = *(const float4*)&s[i];
    float vv[4] = {v.x, v.y, v.z, v.w};
    __nv_bfloat16 hb[4], lb[4];
#pragma unroll
    for (int e = 0; e < 4; e++) {
        hb[e] = __float2bfloat16(vv[e]);
        lb[e] = __float2bfloat16(vv[e] - __bfloat162float(hb[e]));
    }
    *(uint2*)&h[i] = *(uint2*)hb;
    *(uint2*)&l[i] = *(uint2*)lb;
}

// ---------------------------------------------------------------------------
// GEMM: C[M,N] = A[M,K] . B[N,K]^T, bf16 hi/lo compensated.
// 3-stage cp.async pipeline, ONE __syncthreads per K-tile.
// ---------------------------------------------------------------------------
#define GSTAGE 32768
#define GSMEM  (3 * GSTAGE)

__global__ __launch_bounds__(256) void gemm_mma(
    const __nv_bfloat16* __restrict__ Ah, const __nv_bfloat16* __restrict__ Al,
    const __nv_bfloat16* __restrict__ Bh, const __nv_bfloat16* __restrict__ Bl,
    float* __restrict__ C, int M, int N, int K)
{
    extern __shared__ __align__(1024) char smem[];
    const uint32_t sb = smem_u32(smem);
    const int t = threadIdx.x;
    const int wid = t >> 5, lane = t & 31;
    const int m0 = blockIdx.y * 128, n0 = blockIdx.x * 128;
    const int wm = (wid & 3) * 32;
    const int wn = (wid >> 2) * 64;

    const size_t kb = (size_t)K * 2;
    const char* gA[4] = {
        (const char*)(Ah + (size_t)m0 * K), (const char*)(Al + (size_t)m0 * K),
        (const char*)(Bh + (size_t)n0 * K), (const char*)(Bl + (size_t)n0 * K)};

    const int r_ld = t >> 2, cu_ld = t & 3;
    const uint32_t so0 = toff(r_ld, cu_ld);
    const int r_ld2 = (t + 256) >> 2;
    const int cu_ld2 = (t + 256) & 3;
    const uint32_t so1 = toff(r_ld2 & 127, cu_ld2);

    const int nt = K / 32;

    auto issue = [&](int stage, int k0) {
        uint32_t sg = sb + stage * GSTAGE;
#pragma unroll
        for (int tile = 0; tile < 4; tile++) {
            const char* g = gA[tile] + (size_t)k0 * 2;
            uint32_t stb = sg + tile * 8192;
            CP_ASYNC16(stb + so0, g + (size_t)r_ld * kb + cu_ld * 16);
            CP_ASYNC16(stb + so1, g + (size_t)r_ld2 * kb + cu_ld2 * 16);
        }
        CP_COMMIT();
    };

    float acc[2][8][4];
#pragma unroll
    for (int i = 0; i < 2; i++)
#pragma unroll
        for (int j = 0; j < 8; j++)
#pragma unroll
            for (int e = 0; e < 4; e++) acc[i][j][e] = 0.f;

    // prologue: stages 0,1 in flight
    issue(0, 0);
    issue(1, 32);

    const int a_row = (lane & 7) + ((lane >> 3) & 1) * 8;
    const int a_ku  = lane >> 4;
    const int b_row = (lane & 7) + ((lane >> 4) & 1) * 8;
    const int b_ku  = (lane >> 3) & 1;

    for (int tt = 0; tt < nt; tt++) {
        CP_WAIT1();              // group tt complete (<=1 pending)
        __syncthreads();         // all warps done with the stage being refilled

        if (tt + 2 < nt) {
            int s = tt + 2; s -= (s / 3) * 3;
            issue(s, (tt + 2) * 32);
        } else {
            CP_COMMIT();         // empty group keeps accounting uniform
        }
        int cs = tt; cs -= (cs / 3) * 3;
        const uint32_t stg = sb + cs * GSTAGE;

#pragma unroll
        for (int ks = 0; ks < 2; ks++) {
            const int ku = ks * 2;
            uint32_t ah[2][4], al[2][4];
#pragma unroll
            for (int i = 0; i < 2; i++) {
                uint32_t ad = stg + toff(wm + i * 16 + a_row, ku + a_ku);
                LDSM4A(ah[i], ad);
                LDSM4A(al[i], ad + 8192);
            }
#pragma unroll
            for (int jj = 0; jj < 4; jj++) {
                uint32_t bd = stg + 16384 + toff(wn + jj * 16 + b_row, ku + b_ku);
                uint32_t bh[4], bl[4];
                LDSM4A(bh, bd);
                LDSM4A(bl, bd + 8192);
#pragma unroll
                for (int i = 0; i < 2; i++) {
                    MMA16816(acc[i][jj * 2],     ah[i][0], ah[i][1], ah[i][2], ah[i][3], bh[0], bh[1]);
                    MMA16816(acc[i][jj * 2],     ah[i][0], ah[i][1], ah[i][2], ah[i][3], bl[0], bl[1]);
                    MMA16816(acc[i][jj * 2],     al[i][0], al[i][1], al[i][2], al[i][3], bh[0], bh[1]);
                    MMA16816(acc[i][jj * 2 + 1], ah[i][0], ah[i][1], ah[i][2], ah[i][3], bh[2], bh[3]);
                    MMA16816(acc[i][jj * 2 + 1], ah[i][0], ah[i][1], ah[i][2], ah[i][3], bl[2], bl[3]);
                    MMA16816(acc[i][jj * 2 + 1], al[i][0], al[i][1], al[i][2], al[i][3], bh[2], bh[3]);
                }
            }
        }
    }

#pragma unroll
    for (int i = 0; i < 2; i++) {
#pragma unroll
        for (int j = 0; j < 8; j++) {
            int row = m0 + wm + i * 16 + (lane >> 2);
            int col = n0 + wn + j * 8 + (lane & 3) * 2;
            *(float2*)&C[(size_t)row * N + col] = make_float2(acc[i][j][0], acc[i][j][1]);
            *(float2*)&C[(size_t)(row + 8) * N + col] = make_float2(acc[i][j][2], acc[i][j][3]);
        }
    }
}

// ---------------------------------------------------------------------------
// RoPE table + RoPE (q scale folded) -> bf16 hi/lo, and V transpose
// ---------------------------------------------------------------------------
__global__ void rope_tab()
{
    int j = threadIdx.x;
    if (j < 64) g_invf[j] = (float)pow(10000.0, -(double)j / 64.0);
}

__global__ void rope_qk()
{
    int bt   = blockIdx.x;
    int tpos = bt % NT;
    int b    = bt / NT;
    int d    = threadIdx.x;
    int j    = d & 63;

    float invf = g_invf[j];
    float ang = (float)tpos * invf;
    float cv = cosf(ang), sv = sinf(ang);
    float sgn = (d < 64) ? -1.f : 1.f;
    const float* base = g_qkv + (size_t)bt * (3 * NC);
    const float scale = 0.088388347648318447f;

#pragma unroll
    for (int h = 0; h < NH; h++) {
        float qv = base[h * ND + d];
        float qp = base[h * ND + (d ^ 64)];
        float kv = base[NC + h * ND + d];
        float kp = base[NC + h * ND + (d ^ 64)];
        float qo = (qv * cv + sgn * qp * sv) * scale;
        float ko = kv * cv + sgn * kp * sv;
        size_t oi = ((size_t)(b * NH + h) * NT + tpos) * ND + d;
        __nv_bfloat16 qh = __float2bfloat16(qo);
        __nv_bfloat16 kh = __float2bfloat16(ko);
        g_qh[oi] = qh; g_ql[oi] = __float2bfloat16(qo - __bfloat162float(qh));
        g_kh[oi] = kh; g_kl[oi] = __float2bfloat16(ko - __bfloat162float(kh));
    }
}

// V transpose: g_qkv v-part [bt][h*128+d] -> g_vth/g_vtl [bh][d][t]
__global__ void vt_split()
{
    __shared__ float tile[64][132];
    int t0 = blockIdx.x * 64;
    int h  = blockIdx.y;
    int b  = blockIdx.z;
    int t  = threadIdx.x;

#pragma unroll
    for (int i = 0; i < 8; i++) {
        int id = t + 256 * i;
        int r = id >> 5, c4 = (id & 31) * 4;
        float4 v = *(const float4*)&g_qkv[(size_t)(b * NT + t0 + r) * (3 * NC) + 2 * NC + h * ND + c4];
        *(float4*)&tile[r][c4] = v;
    }
    __syncthreads();

    int d = t >> 1, j0 = (t & 1) * 32;
    size_t out = ((size_t)(b * NH + h) * ND + d) * NT + t0 + j0;
#pragma unroll
    for (int jj = 0; jj < 32; jj += 2) {
        float v0 = tile[j0 + jj][d], v1 = tile[j0 + jj + 1][d];
        split_store2(g_vth, g_vtl, out + jj, v0, v1);
    }
}

// ---------------------------------------------------------------------------
// Sliding-window flash attention on mma.sync bf16, fully hi/lo compensated.
// CTA: 128 queries of one (b,h); 8 warps, warp = 16 rows x all keys.
// Key tiles of 64. Q (hi+lo) resident in smem 64KB; K/V double-buffered.
// Warp-level tile skipping for fully-masked tiles.
// ---------------------------------------------------------------------------
#define AQ 128
#define AK 64
#define ASTG 65536
#define ATT_SMEM (65536 + 2 * ASTG)

__global__ __launch_bounds__(256, 1) void swa_mma()
{
    extern __shared__ __align__(1024) char smem[];
    const uint32_t sb = smem_u32(smem);
    const int t = threadIdx.x, wid = t >> 5, lane = t & 31;
    const int q0 = blockIdx.x * AQ;
    const int h = blockIdx.y, b = blockIdx.z;
    const int bh = b * NH + h;
    const size_t hoff = (size_t)bh * NT;

    const uint32_t QH = sb, QL = sb + 32768;

    {
        const char* gq_h = (const char*)(g_qh + (hoff + q0) * ND);
        const char* gq_l = (const char*)(g_ql + (hoff + q0) * ND);
#pragma unroll
        for (int i = 0; i < 8; i++) {
            int id = t + 256 * i;
            int r = id >> 4, u = id & 15;
            uint32_t off = q_off(r, u);
            CP_ASYNC16(QH + off, gq_h + (size_t)r * 256 + u * 16);
            CP_ASYNC16(QL + off, gq_l + (size_t)r * 256 + u * 16);
        }
        CP_COMMIT();
    }

    auto stage_load = [&](int buf, int kt) {
        uint32_t S = sb + 65536 + buf * ASTG;
        const char* gk_h = (const char*)(g_kh + (hoff + kt) * ND);
        const char* gk_l = (const char*)(g_kl + (hoff + kt) * ND);
#pragma unroll
        for (int i = 0; i < 4; i++) {
            int id = t + 256 * i;
            int r = id >> 4, u = id & 15;
            uint32_t off = q_off(r, u);
            CP_ASYNC16(S + off,         gk_h + (size_t)r * 256 + u * 16);
            CP_ASYNC16(S + 16384 + off, gk_l + (size_t)r * 256 + u * 16);
        }
#pragma unroll
        for (int i = 0; i < 4; i++) {
            int id = t + 256 * i;
            int r = id >> 3, u = id & 7;
            uint32_t off = vt_off(r, u);
            size_t gb = ((size_t)(bh * ND + r) * NT + kt + u * 8) * 2;
            CP_ASYNC16(S + 32768 + off, (const char*)g_vth + gb);
            CP_ASYNC16(S + 49152 + off, (const char*)g_vtl + gb);
        }
        CP_COMMIT();
    };

    int kt0 = q0 - NW; if (kt0 < 0) kt0 = 0;
    const int nt = (q0 + AQ - kt0) / AK;

    stage_load(0, kt0);

    float ov[16][4];
#pragma unroll
    for (int jj = 0; jj < 16; jj++)
#pragma unroll
        for (int e = 0; e < 4; e++) ov[jj][e] = 0.f;
    float mrow0 = -1e30f, mrow1 = -1e30f, lrow0 = 0.f, lrow1 = 0.f;

    const int wrow = wid * 16;
    const int a_row = (lane & 7) + ((lane >> 3) & 1) * 8;
    const int a_ku  = lane >> 4;
    const int b_row = (lane & 7) + ((lane >> 4) & 1) * 8;
    const int b_ku  = (lane >> 3) & 1;
    const int r0g = q0 + wrow + (lane >> 2);

    for (int tt = 0; tt < nt; tt++) {
        const int kt = kt0 + tt * AK;
        if (tt + 1 < nt) { stage_load((tt + 1) & 1, kt + AK); CP_WAIT1(); }
        else             { CP_WAIT0(); }
        __syncthreads();
        const uint32_t S = sb + 65536 + (tt & 1) * ASTG;

        // warp-level skip: tile fully outside this warp's causal/window range
        const bool active = (kt <= q0 + wrow + 15) && (kt + AK - 1 >= q0 + wrow - NW);
        if (active) {

        // ---- S = Q.K^T (compensated) ----
        float sc[8][4];
#pragma unroll
        for (int f = 0; f < 8; f++)
#pragma unroll
            for (int e = 0; e < 4; e++) sc[f][e] = 0.f;

#pragma unroll
        for (int ku = 0; ku < 8; ku++) {
            uint32_t qh[4], ql[4];
            uint32_t qa = QH + q_off(wrow + a_row, 2 * ku + a_ku);
            LDSM4A(qh, qa);
            LDSM4A(ql, qa + 32768);
#pragma unroll
            for (int nj = 0; nj < 4; nj++) {
                uint32_t kh[4], kl[4];
                uint32_t ka = S + q_off(nj * 16 + b_row, 2 * ku + b_ku);
                LDSM4A(kh, ka);
                LDSM4A(kl, ka + 16384);
                MMA16816(sc[nj * 2],     qh[0], qh[1], qh[2], qh[3], kh[0], kh[1]);
                MMA16816(sc[nj * 2],     qh[0], qh[1], qh[2], qh[3], kl[0], kl[1]);
                MMA16816(sc[nj * 2],     ql[0], ql[1], ql[2], ql[3], kh[0], kh[1]);
                MMA16816(sc[nj * 2 + 1], qh[0], qh[1], qh[2], qh[3], kh[2], kh[3]);
                MMA16816(sc[nj * 2 + 1], qh[0], qh[1], qh[2], qh[3], kl[2], kl[3]);
                MMA16816(sc[nj * 2 + 1], ql[0], ql[1], ql[2], ql[3], kh[2], kh[3]);
            }
        }

        // ---- mask (only boundary tiles) ----
        const bool cmask = (kt + AK - 1 > q0 + wrow);
        const bool wmask = (kt < q0 + wrow + 15 - NW);
        if (cmask || wmask) {
#pragma unroll
            for (int f = 0; f < 8; f++) {
                int jb = kt + f * 8 + (lane & 3) * 2;
#pragma unroll
                for (int e = 0; e < 2; e++) {
                    int jg = jb + e;
                    if (jg > r0g || jg < r0g - NW)             sc[f][e]     = -1e30f;
                    if (jg > r0g + 8 || jg < r0g + 8 - NW)     sc[f][e + 2] = -1e30f;
                }
            }
        }

        // ---- online softmax (warp-local) ----
        float mt0 = -1e30f, mt1 = -1e30f;
#pragma unroll
        for (int f = 0; f < 8; f++) {
            mt0 = fmaxf(mt0, fmaxf(sc[f][0], sc[f][1]));
            mt1 = fmaxf(mt1, fmaxf(sc[f][2], sc[f][3]));
        }
        mt0 = fmaxf(mt0, __shfl_xor_sync(0xffffffffu, mt0, 1));
        mt0 = fmaxf(mt0, __shfl_xor_sync(0xffffffffu, mt0, 2));
        mt1 = fmaxf(mt1, __shfl_xor_sync(0xffffffffu, mt1, 1));
        mt1 = fmaxf(mt1, __shfl_xor_sync(0xffffffffu, mt1, 2));

        float mn0 = fmaxf(mrow0, mt0), mn1 = fmaxf(mrow1, mt1);
        float al0 = __expf(mrow0 - mn0), al1 = __expf(mrow1 - mn1);
        mrow0 = mn0; mrow1 = mn1;

        float rs0 = 0.f, rs1 = 0.f;
#pragma unroll
        for (int f = 0; f < 8; f++) {
            sc[f][0] = __expf(sc[f][0] - mn0);
            sc[f][1] = __expf(sc[f][1] - mn0);
            sc[f][2] = __expf(sc[f][2] - mn1);
            sc[f][3] = __expf(sc[f][3] - mn1);
            rs0 += sc[f][0] + sc[f][1];
            rs1 += sc[f][2] + sc[f][3];
        }
        rs0 += __shfl_xor_sync(0xffffffffu, rs0, 1);
        rs0 += __shfl_xor_sync(0xffffffffu, rs0, 2);
        rs1 += __shfl_xor_sync(0xffffffffu, rs1, 1);
        rs1 += __shfl_xor_sync(0xffffffffu, rs1, 2);
        lrow0 = lrow0 * al0 + rs0;
        lrow1 = lrow1 * al1 + rs1;

#pragma unroll
        for (int jj = 0; jj < 16; jj++) {
            ov[jj][0] *= al0; ov[jj][1] *= al0;
            ov[jj][2] *= al1; ov[jj][3] *= al1;
        }

        // ---- O += P.V with P hi/lo compensation ----
#pragma unroll
        for (int ks = 0; ks < 4; ks++) {
            uint32_t ph0, pl0, ph1, pl1, ph2, pl2, ph3, pl3;
            packsplit2(sc[2 * ks][0],     sc[2 * ks][1],     ph0, pl0);
            packsplit2(sc[2 * ks][2],     sc[2 * ks][3],     ph1, pl1);
            packsplit2(sc[2 * ks + 1][0], sc[2 * ks + 1][1], ph2, pl2);
            packsplit2(sc[2 * ks + 1][2], sc[2 * ks + 1][3], ph3, pl3);
#pragma unroll
            for (int nj = 0; nj < 8; nj++) {
                uint32_t vh[4], vl[4];
                uint32_t va = S + 32768 + vt_off(nj * 16 + b_row, ks * 2 + b_ku);
                LDSM4A(vh, va);
                LDSM4A(vl, va + 16384);
                MMA16816(ov[nj * 2],     ph0, ph1, ph2, ph3, vh[0], vh[1]);
                MMA16816(ov[nj * 2],     ph0, ph1, ph2, ph3, vl[0], vl[1]);
                MMA16816(ov[nj * 2],     pl0, pl1, pl2, pl3, vh[0], vh[1]);
                MMA16816(ov[nj * 2 + 1], ph0, ph1, ph2, ph3, vh[2], vh[3]);
                MMA16816(ov[nj * 2 + 1], ph0, ph1, ph2, ph3, vl[2], vl[3]);
                MMA16816(ov[nj * 2 + 1], pl0, pl1, pl2, pl3, vh[2], vh[3]);
            }
        }

        }   // active
        __syncthreads();
    }

    // ---- finalize: write hi/lo bf16 directly for the out-projection ----
    float i0 = 1.f / lrow0, i1 = 1.f / lrow1;
    size_t row0 = (size_t)(b * NT + r0g) * NC;
    size_t row1 = row0 + 8 * NC;
#pragma unroll
    for (int jj = 0; jj < 16; jj++) {
        int c = h * ND + jj * 8 + (lane & 3) * 2;
        split_store2(g_ah, g_al, row0 + c, ov[jj][0] * i0, ov[jj][1] * i0);
        split_store2(g_ah, g_al, row1 + c, ov[jj][2] * i1, ov[jj][3] * i1);
    }
}

// ---------------------------------------------------------------------------
extern "C" void kernel_launch(void* const* d_in, const int* in_sizes, int n_in,
                              void* d_out, int out_size)
{
    const float* x     = (const float*)d_in[0];
    const float* w_qkv = (const float*)d_in[1];
    const float* w_o   = (const float*)d_in[2];
    float* out = (float*)d_out;

    float* qkv_ptr;
    cudaGetSymbolAddress((void**)&qkv_ptr, g_qkv);
    __nv_bfloat16 *xh, *xl, *wqh, *wql, *woh, *wol, *ah, *al;
    cudaGetSymbolAddress((void**)&xh, g_xh);   cudaGetSymbolAddress((void**)&xl, g_xl);
    cudaGetSymbolAddress((void**)&wqh, g_wqh); cudaGetSymbolAddress((void**)&wql, g_wql);
    cudaGetSymbolAddress((void**)&woh, g_woh); cudaGetSymbolAddress((void**)&wol, g_wol);
    cudaGetSymbolAddress((void**)&ah, g_ah);   cudaGetSymbolAddress((void**)&al, g_al);

    cudaFuncSetAttribute(gemm_mma, cudaFuncAttributeMaxDynamicSharedMemorySize, GSMEM);
    cudaFuncSetAttribute(swa_mma, cudaFuncAttributeMaxDynamicSharedMemorySize, ATT_SMEM);

    const int M = NB * NT;

    rope_tab<<<1, 64>>>();
    conv_split<<<M * NC / 1024, 256>>>(x, xh, xl, M * NC);
    conv_split<<<3 * NC * NC / 1024, 256>>>(w_qkv, wqh, wql, 3 * NC * NC);
    conv_split<<<NC * NC / 1024, 256>>>(w_o, woh, wol, NC * NC);

    gemm_mma<<<dim3(3 * NC / 128, M / 128), 256, GSMEM>>>(xh, xl, wqh, wql,
                                                          qkv_ptr, M, 3 * NC, NC);
    rope_qk<<<M, ND>>>();
    vt_split<<<dim3(NT / 64, NH, NB), 256>>>();

    swa_mma<<<dim3(NT / AQ, NH, NB), 256, ATT_SMEM>>>();

    gemm_mma<<<dim3(NC / 128, M / 128), 256, GSMEM>>>(ah, al, woh, wol,
                                                      out, M, NC, NC);
}

// round 15
// speedup vs baseline: 1.4189x; 1.4189x over previous
#include <cuda_runtime.h>
#include <cuda_bf16.h>
#include <cuda_fp16.h>
#include <math.h>
#include <cstdint>

#define NB 2
#define NT 4096
#define NC 1024
#define NH 8
#define ND 128
#define NW 512

// ---------------- scratch (__device__ globals; no allocs allowed) ----------
__device__ float g_qkv[NB * NT * 3 * NC];   // [B*T, 3C]
__device__ float g_invf[64];

__device__ __align__(256) __half g_xh[NB * NT * NC], g_xl[NB * NT * NC];
__device__ __align__(256) __half g_wqh[3 * NC * NC];
__device__ __align__(256) __half g_woh[NC * NC];
__device__ __align__(256) __half g_ah[NB * NT * NC], g_al[NB * NT * NC];

__device__ __align__(256) __nv_bfloat16 g_qh[NB * NH * NT * ND], g_ql[NB * NH * NT * ND];
__device__ __align__(256) __nv_bfloat16 g_kh[NB * NH * NT * ND], g_kl[NB * NH * NT * ND];
__device__ __align__(256) __nv_bfloat16 g_vth[NB * NH * ND * NT], g_vtl[NB * NH * ND * NT]; // [bh][d][t]

// ---------------- helpers ---------------------------------------------------
__device__ __forceinline__ uint32_t smem_u32(const void* p) {
    uint32_t a;
    asm("{ .reg .u64 t; cvta.to.shared.u64 t, %1; cvt.u32.u64 %0, t; }" : "=r"(a) : "l"(p));
    return a;
}
// 64B-row packed tile swizzle (two 64B gmem rows per 128B smem row)
__device__ __forceinline__ uint32_t toff(int r, int cu) {
    uint32_t o = ((uint32_t)(r >> 1) << 7) + ((uint32_t)(r & 1) << 6) + ((uint32_t)cu << 4);
    return o ^ ((o >> 3) & 0x70);
}
// 256B-row tile swizzle (u in 0..15) and 128B-row tile swizzle (u in 0..7)
__device__ __forceinline__ uint32_t q_off(int r, int u)  { return (uint32_t)(r * 256 + ((u ^ (r & 7)) << 4)); }
__device__ __forceinline__ uint32_t vt_off(int r, int u) { return (uint32_t)(r * 128 + ((u ^ (r & 7)) << 4)); }

#define LDSM4(r0, r1, r2, r3, ad) \
    asm volatile("ldmatrix.sync.aligned.m8n8.x4.shared.b16 {%0,%1,%2,%3}, [%4];" \
                 : "=r"(r0), "=r"(r1), "=r"(r2), "=r"(r3) : "r"(ad))
#define LDSM4A(a, ad) LDSM4((a)[0], (a)[1], (a)[2], (a)[3], ad)

#define MMA16816(d, a0, a1, a2, a3, b0, b1) \
    asm volatile("mma.sync.aligned.m16n8k16.row.col.f32.bf16.bf16.f32 " \
                 "{%0,%1,%2,%3},{%4,%5,%6,%7},{%8,%9},{%0,%1,%2,%3};" \
                 : "+f"((d)[0]), "+f"((d)[1]), "+f"((d)[2]), "+f"((d)[3]) \
                 : "r"(a0), "r"(a1), "r"(a2), "r"(a3), "r"(b0), "r"(b1))

#define MMA16816H(d, a0, a1, a2, a3, b0, b1) \
    asm volatile("mma.sync.aligned.m16n8k16.row.col.f32.f16.f16.f32 " \
                 "{%0,%1,%2,%3},{%4,%5,%6,%7},{%8,%9},{%0,%1,%2,%3};" \
                 : "+f"((d)[0]), "+f"((d)[1]), "+f"((d)[2]), "+f"((d)[3]) \
                 : "r"(a0), "r"(a1), "r"(a2), "r"(a3), "r"(b0), "r"(b1))

#define CP_ASYNC16(sa, ga) \
    asm volatile("cp.async.cg.shared.global [%0], [%1], 16;" :: "r"(sa), "l"(ga))
#define CP_COMMIT() asm volatile("cp.async.commit_group;" ::: "memory")
#define CP_WAIT0()  asm volatile("cp.async.wait_group 0;" ::: "memory")
#define CP_WAIT1()  asm volatile("cp.async.wait_group 1;" ::: "memory")

__device__ __forceinline__ void packsplit2(float a, float b, uint32_t& hi, uint32_t& lo) {
    __nv_bfloat16 ha = __float2bfloat16(a), hb = __float2bfloat16(b);
    __nv_bfloat162 hp; hp.x = ha; hp.y = hb;
    __nv_bfloat162 lp;
    lp.x = __float2bfloat16(a - __bfloat162float(ha));
    lp.y = __float2bfloat16(b - __bfloat162float(hb));
    hi = *reinterpret_cast<uint32_t*>(&hp);
    lo = *reinterpret_cast<uint32_t*>(&lp);
}
__device__ __forceinline__ void split_store2(__nv_bfloat16* H, __nv_bfloat16* L,
                                             size_t idx, float a, float b) {
    uint32_t hi, lo;
    packsplit2(a, b, hi, lo);
    *reinterpret_cast<uint32_t*>(&H[idx]) = hi;
    *reinterpret_cast<uint32_t*>(&L[idx]) = lo;
}
__device__ __forceinline__ void split_store2h(__half* H, __half* L,
                                              size_t idx, float a, float b) {
    __half ha = __float2half_rn(a), hb = __float2half_rn(b);
    __half2 hp = __halves2half2(ha, hb);
    __half2 lp = __halves2half2(__float2half_rn(a - __half2float(ha)),
                                __float2half_rn(b - __half2float(hb)));
    *reinterpret_cast<uint32_t*>(&H[idx]) = *reinterpret_cast<uint32_t*>(&hp);
    *reinterpret_cast<uint32_t*>(&L[idx]) = *reinterpret_cast<uint32_t*>(&lp);
}

// ---------------------------------------------------------------------------
// fp32 -> (hi, lo) fp16 split (activations)
// ---------------------------------------------------------------------------
__global__ void conv_split_h(const float* __restrict__ s, __half* __restrict__ h,
                             __half* __restrict__ l, int n)
{
    int i = (blockIdx.x * 256 + threadIdx.x) * 4;
    if (i >= n) return;
    float4 v = *(const float4*)&s[i];
    float vv[4] = {v.x, v.y, v.z, v.w};
    __half hb[4], lb[4];
#pragma unroll
    for (int e = 0; e < 4; e++) {
        hb[e] = __float2half_rn(vv[e]);
        lb[e] = __float2half_rn(vv[e] - __half2float(hb[e]));
    }
    *(uint2*)&h[i] = *(uint2*)hb;
    *(uint2*)&l[i] = *(uint2*)lb;
}

// fp32 -> fp16 round (weights, hi only)
__global__ void conv_round_h(const float* __restrict__ s, __half* __restrict__ h, int n)
{
    int i = (blockIdx.x * 256 + threadIdx.x) * 4;
    if (i >= n) return;
    float4 v = *(const float4*)&s[i];
    __half hb[4] = {__float2half_rn(v.x), __float2half_rn(v.y),
                    __float2half_rn(v.z), __float2half_rn(v.w)};
    *(uint2*)&h[i] = *(uint2*)hb;
}

// ---------------------------------------------------------------------------
// GEMM: C[M,N] = A[M,K] . B[N,K]^T, fp16 2-term compensated:
//   C = Ah.Bh + Al.Bh   (B single-rounded fp16; dropped A.Bl ~ 1.6e-4 rel)
// 256 threads, K-tile 32, 3-stage cp.async, ONE __syncthreads per K-tile.
// Stage: Ah | Al | Bh tiles, 8KB each (24KB/stage).
// ---------------------------------------------------------------------------
#define GSTAGE 24576
#define GSMEM  (3 * GSTAGE)

__global__ __launch_bounds__(256) void gemm_mma(
    const __half* __restrict__ Ah, const __half* __restrict__ Al,
    const __half* __restrict__ Bh,
    float* __restrict__ C, int M, int N, int K)
{
    extern __shared__ __align__(1024) char smem[];
    const uint32_t sb = smem_u32(smem);
    const int t = threadIdx.x;
    const int wid = t >> 5, lane = t & 31;
    const int m0 = blockIdx.y * 128, n0 = blockIdx.x * 128;
    const int wm = (wid & 3) * 32;
    const int wn = (wid >> 2) * 64;

    const size_t kb = (size_t)K * 2;
    const char* gA[3] = {
        (const char*)(Ah + (size_t)m0 * K), (const char*)(Al + (size_t)m0 * K),
        (const char*)(Bh + (size_t)n0 * K)};

    const int r_ld = t >> 2, cu_ld = t & 3;
    const uint32_t so0 = toff(r_ld, cu_ld);
    const int r_ld2 = (t + 256) >> 2;
    const int cu_ld2 = (t + 256) & 3;
    const uint32_t so1 = toff(r_ld2 & 127, cu_ld2);

    const int nt = K / 32;

    auto issue = [&](int stage, int k0) {
        uint32_t sg = sb + stage * GSTAGE;
#pragma unroll
        for (int tile = 0; tile < 3; tile++) {
            const char* g = gA[tile] + (size_t)k0 * 2;
            uint32_t stb = sg + tile * 8192;
            CP_ASYNC16(stb + so0, g + (size_t)r_ld * kb + cu_ld * 16);
            CP_ASYNC16(stb + so1, g + (size_t)r_ld2 * kb + cu_ld2 * 16);
        }
        CP_COMMIT();
    };

    float acc[2][8][4];
#pragma unroll
    for (int i = 0; i < 2; i++)
#pragma unroll
        for (int j = 0; j < 8; j++)
#pragma unroll
            for (int e = 0; e < 4; e++) acc[i][j][e] = 0.f;

    issue(0, 0);
    issue(1, 32);

    const int a_row = (lane & 7) + ((lane >> 3) & 1) * 8;
    const int a_ku  = lane >> 4;
    const int b_row = (lane & 7) + ((lane >> 4) & 1) * 8;
    const int b_ku  = (lane >> 3) & 1;

    for (int tt = 0; tt < nt; tt++) {
        CP_WAIT1();
        __syncthreads();

        if (tt + 2 < nt) {
            int s = tt + 2; s -= (s / 3) * 3;
            issue(s, (tt + 2) * 32);
        } else {
            CP_COMMIT();
        }
        int cs = tt; cs -= (cs / 3) * 3;
        const uint32_t stg = sb + cs * GSTAGE;

#pragma unroll
        for (int ks = 0; ks < 2; ks++) {
            const int ku = ks * 2;
            uint32_t ah[2][4], al[2][4];
#pragma unroll
            for (int i = 0; i < 2; i++) {
                uint32_t ad = stg + toff(wm + i * 16 + a_row, ku + a_ku);
                LDSM4A(ah[i], ad);
                LDSM4A(al[i], ad + 8192);
            }
#pragma unroll
            for (int jj = 0; jj < 4; jj++) {
                uint32_t bd = stg + 16384 + toff(wn + jj * 16 + b_row, ku + b_ku);
                uint32_t bh[4];
                LDSM4A(bh, bd);
#pragma unroll
                for (int i = 0; i < 2; i++) {
                    MMA16816H(acc[i][jj * 2],     ah[i][0], ah[i][1], ah[i][2], ah[i][3], bh[0], bh[1]);
                    MMA16816H(acc[i][jj * 2],     al[i][0], al[i][1], al[i][2], al[i][3], bh[0], bh[1]);
                    MMA16816H(acc[i][jj * 2 + 1], ah[i][0], ah[i][1], ah[i][2], ah[i][3], bh[2], bh[3]);
                    MMA16816H(acc[i][jj * 2 + 1], al[i][0], al[i][1], al[i][2], al[i][3], bh[2], bh[3]);
                }
            }
        }
    }

#pragma unroll
    for (int i = 0; i < 2; i++) {
#pragma unroll
        for (int j = 0; j < 8; j++) {
            int row = m0 + wm + i * 16 + (lane >> 2);
            int col = n0 + wn + j * 8 + (lane & 3) * 2;
            *(float2*)&C[(size_t)row * N + col] = make_float2(acc[i][j][0], acc[i][j][1]);
            *(float2*)&C[(size_t)(row + 8) * N + col] = make_float2(acc[i][j][2], acc[i][j][3]);
        }
    }
}

// ---------------------------------------------------------------------------
// RoPE table + RoPE (q scale folded) -> bf16 hi/lo, and V transpose
// ---------------------------------------------------------------------------
__global__ void rope_tab()
{
    int j = threadIdx.x;
    if (j < 64) g_invf[j] = (float)pow(10000.0, -(double)j / 64.0);
}

__global__ void rope_qk()
{
    int bt   = blockIdx.x;
    int tpos = bt % NT;
    int b    = bt / NT;
    int d    = threadIdx.x;
    int j    = d & 63;

    float invf = g_invf[j];
    float ang = (float)tpos * invf;
    float cv = cosf(ang), sv = sinf(ang);
    float sgn = (d < 64) ? -1.f : 1.f;
    const float* base = g_qkv + (size_t)bt * (3 * NC);
    const float scale = 0.088388347648318447f;

#pragma unroll
    for (int h = 0; h < NH; h++) {
        float qv = base[h * ND + d];
        float qp = base[h * ND + (d ^ 64)];
        float kv = base[NC + h * ND + d];
        float kp = base[NC + h * ND + (d ^ 64)];
        float qo = (qv * cv + sgn * qp * sv) * scale;
        float ko = kv * cv + sgn * kp * sv;
        size_t oi = ((size_t)(b * NH + h) * NT + tpos) * ND + d;
        __nv_bfloat16 qh = __float2bfloat16(qo);
        __nv_bfloat16 kh = __float2bfloat16(ko);
        g_qh[oi] = qh; g_ql[oi] = __float2bfloat16(qo - __bfloat162float(qh));
        g_kh[oi] = kh; g_kl[oi] = __float2bfloat16(ko - __bfloat162float(kh));
    }
}

// V transpose: g_qkv v-part [bt][h*128+d] -> g_vth/g_vtl [bh][d][t]
__global__ void vt_split()
{
    __shared__ float tile[64][132];
    int t0 = blockIdx.x * 64;
    int h  = blockIdx.y;
    int b  = blockIdx.z;
    int t  = threadIdx.x;

#pragma unroll
    for (int i = 0; i < 8; i++) {
        int id = t + 256 * i;
        int r = id >> 5, c4 = (id & 31) * 4;
        float4 v = *(const float4*)&g_qkv[(size_t)(b * NT + t0 + r) * (3 * NC) + 2 * NC + h * ND + c4];
        *(float4*)&tile[r][c4] = v;
    }
    __syncthreads();

    int d = t >> 1, j0 = (t & 1) * 32;
    size_t out = ((size_t)(b * NH + h) * ND + d) * NT + t0 + j0;
#pragma unroll
    for (int jj = 0; jj < 32; jj += 2) {
        float v0 = tile[j0 + jj][d], v1 = tile[j0 + jj + 1][d];
        split_store2(g_vth, g_vtl, out + jj, v0, v1);
    }
}

// ---------------------------------------------------------------------------
// Sliding-window flash attention on mma.sync bf16, fully hi/lo compensated.
// (round-7 proven mainloop; epilogue now writes fp16 hi/lo for the fp16
//  out-projection)
// ---------------------------------------------------------------------------
#define AQ 128
#define AK 64
#define ASTG 65536
#define ATT_SMEM (65536 + 2 * ASTG)

__global__ __launch_bounds__(256, 1) void swa_mma()
{
    extern __shared__ __align__(1024) char smem[];
    const uint32_t sb = smem_u32(smem);
    const int t = threadIdx.x, wid = t >> 5, lane = t & 31;
    const int q0 = blockIdx.x * AQ;
    const int h = blockIdx.y, b = blockIdx.z;
    const int bh = b * NH + h;
    const size_t hoff = (size_t)bh * NT;

    const uint32_t QH = sb, QL = sb + 32768;

    {
        const char* gq_h = (const char*)(g_qh + (hoff + q0) * ND);
        const char* gq_l = (const char*)(g_ql + (hoff + q0) * ND);
#pragma unroll
        for (int i = 0; i < 8; i++) {
            int id = t + 256 * i;
            int r = id >> 4, u = id & 15;
            uint32_t off = q_off(r, u);
            CP_ASYNC16(QH + off, gq_h + (size_t)r * 256 + u * 16);
            CP_ASYNC16(QL + off, gq_l + (size_t)r * 256 + u * 16);
        }
        CP_COMMIT();
    }

    auto stage_load = [&](int buf, int kt) {
        uint32_t S = sb + 65536 + buf * ASTG;
        const char* gk_h = (const char*)(g_kh + (hoff + kt) * ND);
        const char* gk_l = (const char*)(g_kl + (hoff + kt) * ND);
#pragma unroll
        for (int i = 0; i < 4; i++) {
            int id = t + 256 * i;
            int r = id >> 4, u = id & 15;
            uint32_t off = q_off(r, u);
            CP_ASYNC16(S + off,         gk_h + (size_t)r * 256 + u * 16);
            CP_ASYNC16(S + 16384 + off, gk_l + (size_t)r * 256 + u * 16);
        }
#pragma unroll
        for (int i = 0; i < 4; i++) {
            int id = t + 256 * i;
            int r = id >> 3, u = id & 7;
            uint32_t off = vt_off(r, u);
            size_t gb = ((size_t)(bh * ND + r) * NT + kt + u * 8) * 2;
            CP_ASYNC16(S + 32768 + off, (const char*)g_vth + gb);
            CP_ASYNC16(S + 49152 + off, (const char*)g_vtl + gb);
        }
        CP_COMMIT();
    };

    int kt0 = q0 - NW; if (kt0 < 0) kt0 = 0;
    const int nt = (q0 + AQ - kt0) / AK;

    stage_load(0, kt0);

    float ov[16][4];
#pragma unroll
    for (int jj = 0; jj < 16; jj++)
#pragma unroll
        for (int e = 0; e < 4; e++) ov[jj][e] = 0.f;
    float mrow0 = -1e30f, mrow1 = -1e30f, lrow0 = 0.f, lrow1 = 0.f;

    const int wrow = wid * 16;
    const int a_row = (lane & 7) + ((lane >> 3) & 1) * 8;
    const int a_ku  = lane >> 4;
    const int b_row = (lane & 7) + ((lane >> 4) & 1) * 8;
    const int b_ku  = (lane >> 3) & 1;
    const int r0g = q0 + wrow + (lane >> 2);

    for (int tt = 0; tt < nt; tt++) {
        const int kt = kt0 + tt * AK;
        if (tt + 1 < nt) { stage_load((tt + 1) & 1, kt + AK); CP_WAIT1(); }
        else             { CP_WAIT0(); }
        __syncthreads();
        const uint32_t S = sb + 65536 + (tt & 1) * ASTG;

        const bool active = (kt <= q0 + wrow + 15) && (kt + AK - 1 >= q0 + wrow - NW);
        if (active) {

        float sc[8][4];
#pragma unroll
        for (int f = 0; f < 8; f++)
#pragma unroll
            for (int e = 0; e < 4; e++) sc[f][e] = 0.f;

#pragma unroll
        for (int ku = 0; ku < 8; ku++) {
            uint32_t qh[4], ql[4];
            uint32_t qa = QH + q_off(wrow + a_row, 2 * ku + a_ku);
            LDSM4A(qh, qa);
            LDSM4A(ql, qa + 32768);
#pragma unroll
            for (int nj = 0; nj < 4; nj++) {
                uint32_t kh[4], kl[4];
                uint32_t ka = S + q_off(nj * 16 + b_row, 2 * ku + b_ku);
                LDSM4A(kh, ka);
                LDSM4A(kl, ka + 16384);
                MMA16816(sc[nj * 2],     qh[0], qh[1], qh[2], qh[3], kh[0], kh[1]);
                MMA16816(sc[nj * 2],     qh[0], qh[1], qh[2], qh[3], kl[0], kl[1]);
                MMA16816(sc[nj * 2],     ql[0], ql[1], ql[2], ql[3], kh[0], kh[1]);
                MMA16816(sc[nj * 2 + 1], qh[0], qh[1], qh[2], qh[3], kh[2], kh[3]);
                MMA16816(sc[nj * 2 + 1], qh[0], qh[1], qh[2], qh[3], kl[2], kl[3]);
                MMA16816(sc[nj * 2 + 1], ql[0], ql[1], ql[2], ql[3], kh[2], kh[3]);
            }
        }

        const bool cmask = (kt + AK - 1 > q0 + wrow);
        const bool wmask = (kt < q0 + wrow + 15 - NW);
        if (cmask || wmask) {
#pragma unroll
            for (int f = 0; f < 8; f++) {
                int jb = kt + f * 8 + (lane & 3) * 2;
#pragma unroll
                for (int e = 0; e < 2; e++) {
                    int jg = jb + e;
                    if (jg > r0g || jg < r0g - NW)             sc[f][e]     = -1e30f;
                    if (jg > r0g + 8 || jg < r0g + 8 - NW)     sc[f][e + 2] = -1e30f;
                }
            }
        }

        float mt0 = -1e30f, mt1 = -1e30f;
#pragma unroll
        for (int f = 0; f < 8; f++) {
            mt0 = fmaxf(mt0, fmaxf(sc[f][0], sc[f][1]));
            mt1 = fmaxf(mt1, fmaxf(sc[f][2], sc[f][3]));
        }
        mt0 = fmaxf(mt0, __shfl_xor_sync(0xffffffffu, mt0, 1));
        mt0 = fmaxf(mt0, __shfl_xor_sync(0xffffffffu, mt0, 2));
        mt1 = fmaxf(mt1, __shfl_xor_sync(0xffffffffu, mt1, 1));
        mt1 = fmaxf(mt1, __shfl_xor_sync(0xffffffffu, mt1, 2));

        float mn0 = fmaxf(mrow0, mt0), mn1 = fmaxf(mrow1, mt1);
        float al0 = __expf(mrow0 - mn0), al1 = __expf(mrow1 - mn1);
        mrow0 = mn0; mrow1 = mn1;

        float rs0 = 0.f, rs1 = 0.f;
#pragma unroll
        for (int f = 0; f < 8; f++) {
            sc[f][0] = __expf(sc[f][0] - mn0);
            sc[f][1] = __expf(sc[f][1] - mn0);
            sc[f][2] = __expf(sc[f][2] - mn1);
            sc[f][3] = __expf(sc[f][3] - mn1);
            rs0 += sc[f][0] + sc[f][1];
            rs1 += sc[f][2] + sc[f][3];
        }
        rs0 += __shfl_xor_sync(0xffffffffu, rs0, 1);
        rs0 += __shfl_xor_sync(0xffffffffu, rs0, 2);
        rs1 += __shfl_xor_sync(0xffffffffu, rs1, 1);
        rs1 += __shfl_xor_sync(0xffffffffu, rs1, 2);
        lrow0 = lrow0 * al0 + rs0;
        lrow1 = lrow1 * al1 + rs1;

#pragma unroll
        for (int jj = 0; jj < 16; jj++) {
            ov[jj][0] *= al0; ov[jj][1] *= al0;
            ov[jj][2] *= al1; ov[jj][3] *= al1;
        }

#pragma unroll
        for (int ks = 0; ks < 4; ks++) {
            uint32_t ph0, pl0, ph1, pl1, ph2, pl2, ph3, pl3;
            packsplit2(sc[2 * ks][0],     sc[2 * ks][1],     ph0, pl0);
            packsplit2(sc[2 * ks][2],     sc[2 * ks][3],     ph1, pl1);
            packsplit2(sc[2 * ks + 1][0], sc[2 * ks + 1][1], ph2, pl2);
            packsplit2(sc[2 * ks + 1][2], sc[2 * ks + 1][3], ph3, pl3);
#pragma unroll
            for (int nj = 0; nj < 8; nj++) {
                uint32_t vh[4], vl[4];
                uint32_t va = S + 32768 + vt_off(nj * 16 + b_row, ks * 2 + b_ku);
                LDSM4A(vh, va);
                LDSM4A(vl, va + 16384);
                MMA16816(ov[nj * 2],     ph0, ph1, ph2, ph3, vh[0], vh[1]);
                MMA16816(ov[nj * 2],     ph0, ph1, ph2, ph3, vl[0], vl[1]);
                MMA16816(ov[nj * 2],     pl0, pl1, pl2, pl3, vh[0], vh[1]);
                MMA16816(ov[nj * 2 + 1], ph0, ph1, ph2, ph3, vh[2], vh[3]);
                MMA16816(ov[nj * 2 + 1], ph0, ph1, ph2, ph3, vl[2], vl[3]);
                MMA16816(ov[nj * 2 + 1], pl0, pl1, pl2, pl3, vh[2], vh[3]);
            }
        }

        }   // active
        __syncthreads();
    }

    // ---- finalize: write fp16 hi/lo for the fp16 out-projection ----
    float i0 = 1.f / lrow0, i1 = 1.f / lrow1;
    size_t row0 = (size_t)(b * NT + r0g) * NC;
    size_t row1 = row0 + 8 * NC;
#pragma unroll
    for (int jj = 0; jj < 16; jj++) {
        int c = h * ND + jj * 8 + (lane & 3) * 2;
        split_store2h(g_ah, g_al, row0 + c, ov[jj][0] * i0, ov[jj][1] * i0);
        split_store2h(g_ah, g_al, row1 + c, ov[jj][2] * i1, ov[jj][3] * i1);
    }
}

// ---------------------------------------------------------------------------
extern "C" void kernel_launch(void* const* d_in, const int* in_sizes, int n_in,
                              void* d_out, int out_size)
{
    const float* x     = (const float*)d_in[0];
    const float* w_qkv = (const float*)d_in[1];
    const float* w_o   = (const float*)d_in[2];
    float* out = (float*)d_out;

    float* qkv_ptr;
    cudaGetSymbolAddress((void**)&qkv_ptr, g_qkv);
    __half *xh, *xl, *wqh, *woh, *ah, *al;
    cudaGetSymbolAddress((void**)&xh, g_xh);   cudaGetSymbolAddress((void**)&xl, g_xl);
    cudaGetSymbolAddress((void**)&wqh, g_wqh);
    cudaGetSymbolAddress((void**)&woh, g_woh);
    cudaGetSymbolAddress((void**)&ah, g_ah);   cudaGetSymbolAddress((void**)&al, g_al);

    cudaFuncSetAttribute(gemm_mma, cudaFuncAttributeMaxDynamicSharedMemorySize, GSMEM);
    cudaFuncSetAttribute(swa_mma, cudaFuncAttributeMaxDynamicSharedMemorySize, ATT_SMEM);

    const int M = NB * NT;

    rope_tab<<<1, 64>>>();
    conv_split_h<<<M * NC / 1024, 256>>>(x, xh, xl, M * NC);
    conv_round_h<<<3 * NC * NC / 1024, 256>>>(w_qkv, wqh, 3 * NC * NC);
    conv_round_h<<<NC * NC / 1024, 256>>>(w_o, woh, NC * NC);

    // 1) QKV projection (fp16 2-term)
    gemm_mma<<<dim3(3 * NC / 128, M / 128), 256, GSMEM>>>(xh, xl, wqh,
                                                          qkv_ptr, M, 3 * NC, NC);
    // 2) RoPE + V transpose (bf16, unchanged)
    rope_qk<<<M, ND>>>();
    vt_split<<<dim3(NT / 64, NH, NB), 256>>>();

    // 3) Sliding-window attention (bf16 3-term, fp16 output)
    swa_mma<<<dim3(NT / AQ, NH, NB), 256, ATT_SMEM>>>();

    // 4) Output projection (fp16 2-term)
    gemm_mma<<<dim3(NC / 128, M / 128), 256, GSMEM>>>(ah, al, woh,
                                                      out, M, NC, NC);
}

// round 16
// speedup vs baseline: 1.5366x; 1.0830x over previous
#include <cuda_runtime.h>
#include <cuda_bf16.h>
#include <cuda_fp16.h>
#include <math.h>
#include <cstdint>

#define NB 2
#define NT 4096
#define NC 1024
#define NH 8
#define ND 128
#define NW 512

// ---------------- scratch (__device__ globals; no allocs allowed) ----------
__device__ float g_qkv[NB * NT * 3 * NC];   // [B*T, 3C]
__device__ float g_invf[64];

__device__ __align__(256) __half g_xh[NB * NT * NC], g_xl[NB * NT * NC];
__device__ __align__(256) __half g_wqh[3 * NC * NC];
__device__ __align__(256) __half g_woh[NC * NC];
__device__ __align__(256) __half g_ah[NB * NT * NC], g_al[NB * NT * NC];

__device__ __align__(256) __half g_qh[NB * NH * NT * ND], g_ql[NB * NH * NT * ND];
__device__ __align__(256) __half g_kh[NB * NH * NT * ND];
__device__ __align__(256) __half g_vth[NB * NH * ND * NT], g_vtl[NB * NH * ND * NT]; // [bh][d][t]

// ---------------- helpers ---------------------------------------------------
__device__ __forceinline__ uint32_t smem_u32(const void* p) {
    uint32_t a;
    asm("{ .reg .u64 t; cvta.to.shared.u64 t, %1; cvt.u32.u64 %0, t; }" : "=r"(a) : "l"(p));
    return a;
}
// 64B-row packed tile swizzle (two 64B gmem rows per 128B smem row)
__device__ __forceinline__ uint32_t toff(int r, int cu) {
    uint32_t o = ((uint32_t)(r >> 1) << 7) + ((uint32_t)(r & 1) << 6) + ((uint32_t)cu << 4);
    return o ^ ((o >> 3) & 0x70);
}
// 256B-row tile swizzle (u in 0..15) and 128B-row tile swizzle (u in 0..7)
__device__ __forceinline__ uint32_t q_off(int r, int u)  { return (uint32_t)(r * 256 + ((u ^ (r & 7)) << 4)); }
__device__ __forceinline__ uint32_t vt_off(int r, int u) { return (uint32_t)(r * 128 + ((u ^ (r & 7)) << 4)); }

#define LDSM4(r0, r1, r2, r3, ad) \
    asm volatile("ldmatrix.sync.aligned.m8n8.x4.shared.b16 {%0,%1,%2,%3}, [%4];" \
                 : "=r"(r0), "=r"(r1), "=r"(r2), "=r"(r3) : "r"(ad))
#define LDSM4A(a, ad) LDSM4((a)[0], (a)[1], (a)[2], (a)[3], ad)

#define MMA16816H(d, a0, a1, a2, a3, b0, b1) \
    asm volatile("mma.sync.aligned.m16n8k16.row.col.f32.f16.f16.f32 " \
                 "{%0,%1,%2,%3},{%4,%5,%6,%7},{%8,%9},{%0,%1,%2,%3};" \
                 : "+f"((d)[0]), "+f"((d)[1]), "+f"((d)[2]), "+f"((d)[3]) \
                 : "r"(a0), "r"(a1), "r"(a2), "r"(a3), "r"(b0), "r"(b1))

#define CP_ASYNC16(sa, ga) \
    asm volatile("cp.async.cg.shared.global [%0], [%1], 16;" :: "r"(sa), "l"(ga))
#define CP_COMMIT() asm volatile("cp.async.commit_group;" ::: "memory")
#define CP_WAIT0()  asm volatile("cp.async.wait_group 0;" ::: "memory")
#define CP_WAIT1()  asm volatile("cp.async.wait_group 1;" ::: "memory")

__device__ __forceinline__ uint32_t packh2(float a, float b) {
    __half2 p = __floats2half2_rn(a, b);
    return *reinterpret_cast<uint32_t*>(&p);
}
__device__ __forceinline__ void split_store2h(__half* H, __half* L,
                                              size_t idx, float a, float b) {
    __half ha = __float2half_rn(a), hb = __float2half_rn(b);
    __half2 hp = __halves2half2(ha, hb);
    __half2 lp = __halves2half2(__float2half_rn(a - __half2float(ha)),
                                __float2half_rn(b - __half2float(hb)));
    *reinterpret_cast<uint32_t*>(&H[idx]) = *reinterpret_cast<uint32_t*>(&hp);
    *reinterpret_cast<uint32_t*>(&L[idx]) = *reinterpret_cast<uint32_t*>(&lp);
}

// ---------------------------------------------------------------------------
// fp32 -> (hi, lo) fp16 split (activations)
// ---------------------------------------------------------------------------
__global__ void conv_split_h(const float* __restrict__ s, __half* __restrict__ h,
                             __half* __restrict__ l, int n)
{
    int i = (blockIdx.x * 256 + threadIdx.x) * 4;
    if (i >= n) return;
    float4 v = *(const float4*)&s[i];
    float vv[4] = {v.x, v.y, v.z, v.w};
    __half hb[4], lb[4];
#pragma unroll
    for (int e = 0; e < 4; e++) {
        hb[e] = __float2half_rn(vv[e]);
        lb[e] = __float2half_rn(vv[e] - __half2float(hb[e]));
    }
    *(uint2*)&h[i] = *(uint2*)hb;
    *(uint2*)&l[i] = *(uint2*)lb;
}

// fp32 -> fp16 round (weights, hi only)
__global__ void conv_round_h(const float* __restrict__ s, __half* __restrict__ h, int n)
{
    int i = (blockIdx.x * 256 + threadIdx.x) * 4;
    if (i >= n) return;
    float4 v = *(const float4*)&s[i];
    __half hb[4] = {__float2half_rn(v.x), __float2half_rn(v.y),
                    __float2half_rn(v.z), __float2half_rn(v.w)};
    *(uint2*)&h[i] = *(uint2*)hb;
}

// ---------------------------------------------------------------------------
// GEMM: C[M,N] = A[M,K] . B[N,K]^T, fp16 2-term compensated (round-15 proven)
// ---------------------------------------------------------------------------
#define GSTAGE 24576
#define GSMEM  (3 * GSTAGE)

__global__ __launch_bounds__(256) void gemm_mma(
    const __half* __restrict__ Ah, const __half* __restrict__ Al,
    const __half* __restrict__ Bh,
    float* __restrict__ C, int M, int N, int K)
{
    extern __shared__ __align__(1024) char smem[];
    const uint32_t sb = smem_u32(smem);
    const int t = threadIdx.x;
    const int wid = t >> 5, lane = t & 31;
    const int m0 = blockIdx.y * 128, n0 = blockIdx.x * 128;
    const int wm = (wid & 3) * 32;
    const int wn = (wid >> 2) * 64;

    const size_t kb = (size_t)K * 2;
    const char* gA[3] = {
        (const char*)(Ah + (size_t)m0 * K), (const char*)(Al + (size_t)m0 * K),
        (const char*)(Bh + (size_t)n0 * K)};

    const int r_ld = t >> 2, cu_ld = t & 3;
    const uint32_t so0 = toff(r_ld, cu_ld);
    const int r_ld2 = (t + 256) >> 2;
    const int cu_ld2 = (t + 256) & 3;
    const uint32_t so1 = toff(r_ld2 & 127, cu_ld2);

    const int nt = K / 32;

    auto issue = [&](int stage, int k0) {
        uint32_t sg = sb + stage * GSTAGE;
#pragma unroll
        for (int tile = 0; tile < 3; tile++) {
            const char* g = gA[tile] + (size_t)k0 * 2;
            uint32_t stb = sg + tile * 8192;
            CP_ASYNC16(stb + so0, g + (size_t)r_ld * kb + cu_ld * 16);
            CP_ASYNC16(stb + so1, g + (size_t)r_ld2 * kb + cu_ld2 * 16);
        }
        CP_COMMIT();
    };

    float acc[2][8][4];
#pragma unroll
    for (int i = 0; i < 2; i++)
#pragma unroll
        for (int j = 0; j < 8; j++)
#pragma unroll
            for (int e = 0; e < 4; e++) acc[i][j][e] = 0.f;

    issue(0, 0);
    issue(1, 32);

    const int a_row = (lane & 7) + ((lane >> 3) & 1) * 8;
    const int a_ku  = lane >> 4;
    const int b_row = (lane & 7) + ((lane >> 4) & 1) * 8;
    const int b_ku  = (lane >> 3) & 1;

    for (int tt = 0; tt < nt; tt++) {
        CP_WAIT1();
        __syncthreads();

        if (tt + 2 < nt) {
            int s = tt + 2; s -= (s / 3) * 3;
            issue(s, (tt + 2) * 32);
        } else {
            CP_COMMIT();
        }
        int cs = tt; cs -= (cs / 3) * 3;
        const uint32_t stg = sb + cs * GSTAGE;

#pragma unroll
        for (int ks = 0; ks < 2; ks++) {
            const int ku = ks * 2;
            uint32_t ah[2][4], al[2][4];
#pragma unroll
            for (int i = 0; i < 2; i++) {
                uint32_t ad = stg + toff(wm + i * 16 + a_row, ku + a_ku);
                LDSM4A(ah[i], ad);
                LDSM4A(al[i], ad + 8192);
            }
#pragma unroll
            for (int jj = 0; jj < 4; jj++) {
                uint32_t bd = stg + 16384 + toff(wn + jj * 16 + b_row, ku + b_ku);
                uint32_t bh[4];
                LDSM4A(bh, bd);
#pragma unroll
                for (int i = 0; i < 2; i++) {
                    MMA16816H(acc[i][jj * 2],     ah[i][0], ah[i][1], ah[i][2], ah[i][3], bh[0], bh[1]);
                    MMA16816H(acc[i][jj * 2],     al[i][0], al[i][1], al[i][2], al[i][3], bh[0], bh[1]);
                    MMA16816H(acc[i][jj * 2 + 1], ah[i][0], ah[i][1], ah[i][2], ah[i][3], bh[2], bh[3]);
                    MMA16816H(acc[i][jj * 2 + 1], al[i][0], al[i][1], al[i][2], al[i][3], bh[2], bh[3]);
                }
            }
        }
    }

#pragma unroll
    for (int i = 0; i < 2; i++) {
#pragma unroll
        for (int j = 0; j < 8; j++) {
            int row = m0 + wm + i * 16 + (lane >> 2);
            int col = n0 + wn + j * 8 + (lane & 3) * 2;
            *(float2*)&C[(size_t)row * N + col] = make_float2(acc[i][j][0], acc[i][j][1]);
            *(float2*)&C[(size_t)(row + 8) * N + col] = make_float2(acc[i][j][2], acc[i][j][3]);
        }
    }
}

// ---------------------------------------------------------------------------
// RoPE table + RoPE (q scale folded) -> fp16 (q hi/lo, k single), V transpose
// ---------------------------------------------------------------------------
__global__ void rope_tab()
{
    int j = threadIdx.x;
    if (j < 64) g_invf[j] = (float)pow(10000.0, -(double)j / 64.0);
}

__global__ void rope_qk()
{
    int bt   = blockIdx.x;
    int tpos = bt % NT;
    int b    = bt / NT;
    int d    = threadIdx.x;
    int j    = d & 63;

    float invf = g_invf[j];
    float ang = (float)tpos * invf;
    float cv = cosf(ang), sv = sinf(ang);
    float sgn = (d < 64) ? -1.f : 1.f;
    const float* base = g_qkv + (size_t)bt * (3 * NC);
    const float scale = 0.088388347648318447f;

#pragma unroll
    for (int h = 0; h < NH; h++) {
        float qv = base[h * ND + d];
        float qp = base[h * ND + (d ^ 64)];
        float kv = base[NC + h * ND + d];
        float kp = base[NC + h * ND + (d ^ 64)];
        float qo = (qv * cv + sgn * qp * sv) * scale;
        float ko = kv * cv + sgn * kp * sv;
        size_t oi = ((size_t)(b * NH + h) * NT + tpos) * ND + d;
        __half qh = __float2half_rn(qo);
        g_qh[oi] = qh;
        g_ql[oi] = __float2half_rn(qo - __half2float(qh));
        g_kh[oi] = __float2half_rn(ko);
    }
}

// V transpose: g_qkv v-part [bt][h*128+d] -> g_vth/g_vtl [bh][d][t] (fp16 hi/lo)
__global__ void vt_split()
{
    __shared__ float tile[64][132];
    int t0 = blockIdx.x * 64;
    int h  = blockIdx.y;
    int b  = blockIdx.z;
    int t  = threadIdx.x;

#pragma unroll
    for (int i = 0; i < 8; i++) {
        int id = t + 256 * i;
        int r = id >> 5, c4 = (id & 31) * 4;
        float4 v = *(const float4*)&g_qkv[(size_t)(b * NT + t0 + r) * (3 * NC) + 2 * NC + h * ND + c4];
        *(float4*)&tile[r][c4] = v;
    }
    __syncthreads();

    int d = t >> 1, j0 = (t & 1) * 32;
    size_t out = ((size_t)(b * NH + h) * ND + d) * NT + t0 + j0;
#pragma unroll
    for (int jj = 0; jj < 32; jj += 2) {
        float v0 = tile[j0 + jj][d], v1 = tile[j0 + jj + 1][d];
        split_store2h(g_vth, g_vtl, out + jj, v0, v1);
    }
}

// ---------------------------------------------------------------------------
// Sliding-window flash attention, fp16 2-term compensated:
//   S = Qh.K + Ql.K  (K single-rounded fp16)
//   O = P.Vh + P.Vl  (P single-rounded fp16)
// CTA: 128 queries; 8 warps = 16 rows x all keys; Q smem-resident;
// 2-stage K/V pipeline (48KB/stage); warp-level tile skipping.
// ---------------------------------------------------------------------------
#define AQ 128
#define AK 64
#define ASTG 49152
#define ATT_SMEM (65536 + 2 * ASTG)

__global__ __launch_bounds__(256, 1) void swa_mma()
{
    extern __shared__ __align__(1024) char smem[];
    const uint32_t sb = smem_u32(smem);
    const int t = threadIdx.x, wid = t >> 5, lane = t & 31;
    const int q0 = blockIdx.x * AQ;
    const int h = blockIdx.y, b = blockIdx.z;
    const int bh = b * NH + h;
    const size_t hoff = (size_t)bh * NT;

    const uint32_t QH = sb, QL = sb + 32768;

    {
        const char* gq_h = (const char*)(g_qh + (hoff + q0) * ND);
        const char* gq_l = (const char*)(g_ql + (hoff + q0) * ND);
#pragma unroll
        for (int i = 0; i < 8; i++) {
            int id = t + 256 * i;
            int r = id >> 4, u = id & 15;
            uint32_t off = q_off(r, u);
            CP_ASYNC16(QH + off, gq_h + (size_t)r * 256 + u * 16);
            CP_ASYNC16(QL + off, gq_l + (size_t)r * 256 + u * 16);
        }
        CP_COMMIT();
    }

    auto stage_load = [&](int buf, int kt) {
        uint32_t S = sb + 65536 + buf * ASTG;
        const char* gk = (const char*)(g_kh + (hoff + kt) * ND);
#pragma unroll
        for (int i = 0; i < 4; i++) {
            int id = t + 256 * i;
            int r = id >> 4, u = id & 15;
            CP_ASYNC16(S + q_off(r, u), gk + (size_t)r * 256 + u * 16);
        }
#pragma unroll
        for (int i = 0; i < 4; i++) {
            int id = t + 256 * i;
            int r = id >> 3, u = id & 7;
            uint32_t off = vt_off(r, u);
            size_t gb = ((size_t)(bh * ND + r) * NT + kt + u * 8) * 2;
            CP_ASYNC16(S + 16384 + off, (const char*)g_vth + gb);
            CP_ASYNC16(S + 32768 + off, (const char*)g_vtl + gb);
        }
        CP_COMMIT();
    };

    int kt0 = q0 - NW; if (kt0 < 0) kt0 = 0;
    const int nt = (q0 + AQ - kt0) / AK;

    stage_load(0, kt0);

    float ov[16][4];
#pragma unroll
    for (int jj = 0; jj < 16; jj++)
#pragma unroll
        for (int e = 0; e < 4; e++) ov[jj][e] = 0.f;
    float mrow0 = -1e30f, mrow1 = -1e30f, lrow0 = 0.f, lrow1 = 0.f;

    const int wrow = wid * 16;
    const int a_row = (lane & 7) + ((lane >> 3) & 1) * 8;
    const int a_ku  = lane >> 4;
    const int b_row = (lane & 7) + ((lane >> 4) & 1) * 8;
    const int b_ku  = (lane >> 3) & 1;
    const int r0g = q0 + wrow + (lane >> 2);

    for (int tt = 0; tt < nt; tt++) {
        const int kt = kt0 + tt * AK;
        if (tt + 1 < nt) { stage_load((tt + 1) & 1, kt + AK); CP_WAIT1(); }
        else             { CP_WAIT0(); }
        __syncthreads();
        const uint32_t S = sb + 65536 + (tt & 1) * ASTG;

        const bool active = (kt <= q0 + wrow + 15) && (kt + AK - 1 >= q0 + wrow - NW);
        if (active) {

        // ---- S = Q.K (2-term: Qh.K + Ql.K) ----
        float sc[8][4];
#pragma unroll
        for (int f = 0; f < 8; f++)
#pragma unroll
            for (int e = 0; e < 4; e++) sc[f][e] = 0.f;

#pragma unroll
        for (int ku = 0; ku < 8; ku++) {
            uint32_t qh[4], ql[4];
            uint32_t qa = QH + q_off(wrow + a_row, 2 * ku + a_ku);
            LDSM4A(qh, qa);
            LDSM4A(ql, qa + 32768);
#pragma unroll
            for (int nj = 0; nj < 4; nj++) {
                uint32_t kh[4];
                uint32_t ka = S + q_off(nj * 16 + b_row, 2 * ku + b_ku);
                LDSM4A(kh, ka);
                MMA16816H(sc[nj * 2],     qh[0], qh[1], qh[2], qh[3], kh[0], kh[1]);
                MMA16816H(sc[nj * 2],     ql[0], ql[1], ql[2], ql[3], kh[0], kh[1]);
                MMA16816H(sc[nj * 2 + 1], qh[0], qh[1], qh[2], qh[3], kh[2], kh[3]);
                MMA16816H(sc[nj * 2 + 1], ql[0], ql[1], ql[2], ql[3], kh[2], kh[3]);
            }
        }

        const bool cmask = (kt + AK - 1 > q0 + wrow);
        const bool wmask = (kt < q0 + wrow + 15 - NW);
        if (cmask || wmask) {
#pragma unroll
            for (int f = 0; f < 8; f++) {
                int jb = kt + f * 8 + (lane & 3) * 2;
#pragma unroll
                for (int e = 0; e < 2; e++) {
                    int jg = jb + e;
                    if (jg > r0g || jg < r0g - NW)             sc[f][e]     = -1e30f;
                    if (jg > r0g + 8 || jg < r0g + 8 - NW)     sc[f][e + 2] = -1e30f;
                }
            }
        }

        float mt0 = -1e30f, mt1 = -1e30f;
#pragma unroll
        for (int f = 0; f < 8; f++) {
            mt0 = fmaxf(mt0, fmaxf(sc[f][0], sc[f][1]));
            mt1 = fmaxf(mt1, fmaxf(sc[f][2], sc[f][3]));
        }
        mt0 = fmaxf(mt0, __shfl_xor_sync(0xffffffffu, mt0, 1));
        mt0 = fmaxf(mt0, __shfl_xor_sync(0xffffffffu, mt0, 2));
        mt1 = fmaxf(mt1, __shfl_xor_sync(0xffffffffu, mt1, 1));
        mt1 = fmaxf(mt1, __shfl_xor_sync(0xffffffffu, mt1, 2));

        float mn0 = fmaxf(mrow0, mt0), mn1 = fmaxf(mrow1, mt1);
        float al0 = __expf(mrow0 - mn0), al1 = __expf(mrow1 - mn1);
        mrow0 = mn0; mrow1 = mn1;

        float rs0 = 0.f, rs1 = 0.f;
#pragma unroll
        for (int f = 0; f < 8; f++) {
            sc[f][0] = __expf(sc[f][0] - mn0);
            sc[f][1] = __expf(sc[f][1] - mn0);
            sc[f][2] = __expf(sc[f][2] - mn1);
            sc[f][3] = __expf(sc[f][3] - mn1);
            rs0 += sc[f][0] + sc[f][1];
            rs1 += sc[f][2] + sc[f][3];
        }
        rs0 += __shfl_xor_sync(0xffffffffu, rs0, 1);
        rs0 += __shfl_xor_sync(0xffffffffu, rs0, 2);
        rs1 += __shfl_xor_sync(0xffffffffu, rs1, 1);
        rs1 += __shfl_xor_sync(0xffffffffu, rs1, 2);
        lrow0 = lrow0 * al0 + rs0;
        lrow1 = lrow1 * al1 + rs1;

#pragma unroll
        for (int jj = 0; jj < 16; jj++) {
            ov[jj][0] *= al0; ov[jj][1] *= al0;
            ov[jj][2] *= al1; ov[jj][3] *= al1;
        }

        // ---- O += P.V (P single fp16; V hi/lo) ----
#pragma unroll
        for (int ks = 0; ks < 4; ks++) {
            uint32_t p0 = packh2(sc[2 * ks][0],     sc[2 * ks][1]);
            uint32_t p1 = packh2(sc[2 * ks][2],     sc[2 * ks][3]);
            uint32_t p2 = packh2(sc[2 * ks + 1][0], sc[2 * ks + 1][1]);
            uint32_t p3 = packh2(sc[2 * ks + 1][2], sc[2 * ks + 1][3]);
#pragma unroll
            for (int nj = 0; nj < 8; nj++) {
                uint32_t vh[4], vl[4];
                uint32_t va = S + 16384 + vt_off(nj * 16 + b_row, ks * 2 + b_ku);
                LDSM4A(vh, va);
                LDSM4A(vl, va + 16384);
                MMA16816H(ov[nj * 2],     p0, p1, p2, p3, vh[0], vh[1]);
                MMA16816H(ov[nj * 2],     p0, p1, p2, p3, vl[0], vl[1]);
                MMA16816H(ov[nj * 2 + 1], p0, p1, p2, p3, vh[2], vh[3]);
                MMA16816H(ov[nj * 2 + 1], p0, p1, p2, p3, vl[2], vl[3]);
            }
        }

        }   // active
        __syncthreads();
    }

    // ---- finalize: write fp16 hi/lo for the fp16 out-projection ----
    float i0 = 1.f / lrow0, i1 = 1.f / lrow1;
    size_t row0 = (size_t)(b * NT + r0g) * NC;
    size_t row1 = row0 + 8 * NC;
#pragma unroll
    for (int jj = 0; jj < 16; jj++) {
        int c = h * ND + jj * 8 + (lane & 3) * 2;
        split_store2h(g_ah, g_al, row0 + c, ov[jj][0] * i0, ov[jj][1] * i0);
        split_store2h(g_ah, g_al, row1 + c, ov[jj][2] * i1, ov[jj][3] * i1);
    }
}

// ---------------------------------------------------------------------------
extern "C" void kernel_launch(void* const* d_in, const int* in_sizes, int n_in,
                              void* d_out, int out_size)
{
    const float* x     = (const float*)d_in[0];
    const float* w_qkv = (const float*)d_in[1];
    const float* w_o   = (const float*)d_in[2];
    float* out = (float*)d_out;

    float* qkv_ptr;
    cudaGetSymbolAddress((void**)&qkv_ptr, g_qkv);
    __half *xh, *xl, *wqh, *woh, *ah, *al;
    cudaGetSymbolAddress((void**)&xh, g_xh);   cudaGetSymbolAddress((void**)&xl, g_xl);
    cudaGetSymbolAddress((void**)&wqh, g_wqh);
    cudaGetSymbolAddress((void**)&woh, g_woh);
    cudaGetSymbolAddress((void**)&ah, g_ah);   cudaGetSymbolAddress((void**)&al, g_al);

    cudaFuncSetAttribute(gemm_mma, cudaFuncAttributeMaxDynamicSharedMemorySize, GSMEM);
    cudaFuncSetAttribute(swa_mma, cudaFuncAttributeMaxDynamicSharedMemorySize, ATT_SMEM);

    const int M = NB * NT;

    rope_tab<<<1, 64>>>();
    conv_split_h<<<M * NC / 1024, 256>>>(x, xh, xl, M * NC);
    conv_round_h<<<3 * NC * NC / 1024, 256>>>(w_qkv, wqh, 3 * NC * NC);
    conv_round_h<<<NC * NC / 1024, 256>>>(w_o, woh, NC * NC);

    // 1) QKV projection (fp16 2-term)
    gemm_mma<<<dim3(3 * NC / 128, M / 128), 256, GSMEM>>>(xh, xl, wqh,
                                                          qkv_ptr, M, 3 * NC, NC);
    // 2) RoPE + V transpose (fp16)
    rope_qk<<<M, ND>>>();
    vt_split<<<dim3(NT / 64, NH, NB), 256>>>();

    // 3) Sliding-window attention (fp16 2-term)
    swa_mma<<<dim3(NT / AQ, NH, NB), 256, ATT_SMEM>>>();

    // 4) Output projection (fp16 2-term)
    gemm_mma<<<dim3(NC / 128, M / 128), 256, GSMEM>>>(ah, al, woh,
                                                      out, M, NC, NC);
}

// round 17
// speedup vs baseline: 2.4489x; 1.5937x over previous
#include <cuda_runtime.h>
#include <cuda_fp16.h>
#include <math.h>
#include <cstdint>

#define NB 2
#define NT 4096
#define NC 1024
#define NH 8
#define ND 128
#define NW 512

// ---------------- scratch (__device__ globals; no allocs allowed) ----------
__device__ float g_qkv[NB * NT * 3 * NC];   // [B*T, 3C]
__device__ float g_invf[64];

__device__ __align__(256) __half g_xh[NB * NT * NC];
__device__ __align__(256) __half g_wqh[3 * NC * NC];
__device__ __align__(256) __half g_woh[NC * NC];
__device__ __align__(256) __half g_ah[NB * NT * NC];

__device__ __align__(256) __half g_qh[NB * NH * NT * ND];
__device__ __align__(256) __half g_kh[NB * NH * NT * ND];
__device__ __align__(256) __half g_vth[NB * NH * ND * NT];   // [bh][d][t]

// ---------------- helpers ---------------------------------------------------
__device__ __forceinline__ uint32_t smem_u32(const void* p) {
    uint32_t a;
    asm("{ .reg .u64 t; cvta.to.shared.u64 t, %1; cvt.u32.u64 %0, t; }" : "=r"(a) : "l"(p));
    return a;
}
// 64B-row packed tile swizzle (two 64B gmem rows per 128B smem row)
__device__ __forceinline__ uint32_t toff(int r, int cu) {
    uint32_t o = ((uint32_t)(r >> 1) << 7) + ((uint32_t)(r & 1) << 6) + ((uint32_t)cu << 4);
    return o ^ ((o >> 3) & 0x70);
}
// 256B-row tile swizzle (u in 0..15) and 128B-row tile swizzle (u in 0..7)
__device__ __forceinline__ uint32_t q_off(int r, int u)  { return (uint32_t)(r * 256 + ((u ^ (r & 7)) << 4)); }
__device__ __forceinline__ uint32_t vt_off(int r, int u) { return (uint32_t)(r * 128 + ((u ^ (r & 7)) << 4)); }

#define LDSM4(r0, r1, r2, r3, ad) \
    asm volatile("ldmatrix.sync.aligned.m8n8.x4.shared.b16 {%0,%1,%2,%3}, [%4];" \
                 : "=r"(r0), "=r"(r1), "=r"(r2), "=r"(r3) : "r"(ad))
#define LDSM4A(a, ad) LDSM4((a)[0], (a)[1], (a)[2], (a)[3], ad)

#define MMA16816H(d, a0, a1, a2, a3, b0, b1) \
    asm volatile("mma.sync.aligned.m16n8k16.row.col.f32.f16.f16.f32 " \
                 "{%0,%1,%2,%3},{%4,%5,%6,%7},{%8,%9},{%0,%1,%2,%3};" \
                 : "+f"((d)[0]), "+f"((d)[1]), "+f"((d)[2]), "+f"((d)[3]) \
                 : "r"(a0), "r"(a1), "r"(a2), "r"(a3), "r"(b0), "r"(b1))

#define CP_ASYNC16(sa, ga) \
    asm volatile("cp.async.cg.shared.global [%0], [%1], 16;" :: "r"(sa), "l"(ga))
#define CP_COMMIT() asm volatile("cp.async.commit_group;" ::: "memory")
#define CP_WAIT0()  asm volatile("cp.async.wait_group 0;" ::: "memory")
#define CP_WAIT1()  asm volatile("cp.async.wait_group 1;" ::: "memory")

__device__ __forceinline__ uint32_t packh2(float a, float b) {
    __half2 p = __floats2half2_rn(a, b);
    return *reinterpret_cast<uint32_t*>(&p);
}
__device__ __forceinline__ void store2h(__half* H, size_t idx, float a, float b) {
    *reinterpret_cast<uint32_t*>(&H[idx]) = packh2(a, b);
}

// ---------------------------------------------------------------------------
// fp32 -> fp16 round
// ---------------------------------------------------------------------------
__global__ void conv_round_h(const float* __restrict__ s, __half* __restrict__ h, int n)
{
    int i = (blockIdx.x * 256 + threadIdx.x) * 4;
    if (i >= n) return;
    float4 v = *(const float4*)&s[i];
    __half hb[4] = {__float2half_rn(v.x), __float2half_rn(v.y),
                    __float2half_rn(v.z), __float2half_rn(v.w)};
    *(uint2*)&h[i] = *(uint2*)hb;
}

// ---------------------------------------------------------------------------
// GEMM: C[M,N] = A[M,K] . B[N,K]^T, plain fp16 operands, fp32 accumulate.
// 256 threads, K-tile 32, 3-stage cp.async, ONE __syncthreads per K-tile.
// Stage: A | B tiles, 8KB each (16KB/stage).
// ---------------------------------------------------------------------------
#define GSTAGE 16384
#define GSMEM  (3 * GSTAGE)

__global__ __launch_bounds__(256) void gemm_mma(
    const __half* __restrict__ A, const __half* __restrict__ B,
    float* __restrict__ C, int M, int N, int K)
{
    extern __shared__ __align__(1024) char smem[];
    const uint32_t sb = smem_u32(smem);
    const int t = threadIdx.x;
    const int wid = t >> 5, lane = t & 31;
    const int m0 = blockIdx.y * 128, n0 = blockIdx.x * 128;
    const int wm = (wid & 3) * 32;
    const int wn = (wid >> 2) * 64;

    const size_t kb = (size_t)K * 2;
    const char* gA[2] = {
        (const char*)(A + (size_t)m0 * K), (const char*)(B + (size_t)n0 * K)};

    const int r_ld = t >> 2, cu_ld = t & 3;
    const uint32_t so0 = toff(r_ld, cu_ld);
    const int r_ld2 = (t + 256) >> 2;
    const int cu_ld2 = (t + 256) & 3;
    const uint32_t so1 = toff(r_ld2 & 127, cu_ld2);

    const int nt = K / 32;

    auto issue = [&](int stage, int k0) {
        uint32_t sg = sb + stage * GSTAGE;
#pragma unroll
        for (int tile = 0; tile < 2; tile++) {
            const char* g = gA[tile] + (size_t)k0 * 2;
            uint32_t stb = sg + tile * 8192;
            CP_ASYNC16(stb + so0, g + (size_t)r_ld * kb + cu_ld * 16);
            CP_ASYNC16(stb + so1, g + (size_t)r_ld2 * kb + cu_ld2 * 16);
        }
        CP_COMMIT();
    };

    float acc[2][8][4];
#pragma unroll
    for (int i = 0; i < 2; i++)
#pragma unroll
        for (int j = 0; j < 8; j++)
#pragma unroll
            for (int e = 0; e < 4; e++) acc[i][j][e] = 0.f;

    issue(0, 0);
    issue(1, 32);

    const int a_row = (lane & 7) + ((lane >> 3) & 1) * 8;
    const int a_ku  = lane >> 4;
    const int b_row = (lane & 7) + ((lane >> 4) & 1) * 8;
    const int b_ku  = (lane >> 3) & 1;

    for (int tt = 0; tt < nt; tt++) {
        CP_WAIT1();
        __syncthreads();

        if (tt + 2 < nt) {
            int s = tt + 2; s -= (s / 3) * 3;
            issue(s, (tt + 2) * 32);
        } else {
            CP_COMMIT();
        }
        int cs = tt; cs -= (cs / 3) * 3;
        const uint32_t stg = sb + cs * GSTAGE;

#pragma unroll
        for (int ks = 0; ks < 2; ks++) {
            const int ku = ks * 2;
            uint32_t ah[2][4];
#pragma unroll
            for (int i = 0; i < 2; i++) {
                uint32_t ad = stg + toff(wm + i * 16 + a_row, ku + a_ku);
                LDSM4A(ah[i], ad);
            }
#pragma unroll
            for (int jj = 0; jj < 4; jj++) {
                uint32_t bd = stg + 8192 + toff(wn + jj * 16 + b_row, ku + b_ku);
                uint32_t bh[4];
                LDSM4A(bh, bd);
#pragma unroll
                for (int i = 0; i < 2; i++) {
                    MMA16816H(acc[i][jj * 2],     ah[i][0], ah[i][1], ah[i][2], ah[i][3], bh[0], bh[1]);
                    MMA16816H(acc[i][jj * 2 + 1], ah[i][0], ah[i][1], ah[i][2], ah[i][3], bh[2], bh[3]);
                }
            }
        }
    }

#pragma unroll
    for (int i = 0; i < 2; i++) {
#pragma unroll
        for (int j = 0; j < 8; j++) {
            int row = m0 + wm + i * 16 + (lane >> 2);
            int col = n0 + wn + j * 8 + (lane & 3) * 2;
            *(float2*)&C[(size_t)row * N + col] = make_float2(acc[i][j][0], acc[i][j][1]);
            *(float2*)&C[(size_t)(row + 8) * N + col] = make_float2(acc[i][j][2], acc[i][j][3]);
        }
    }
}

// ---------------------------------------------------------------------------
// RoPE table + RoPE (q scale folded) -> fp16 single, V transpose (fp16 single)
// ---------------------------------------------------------------------------
__global__ void rope_tab()
{
    int j = threadIdx.x;
    if (j < 64) g_invf[j] = (float)pow(10000.0, -(double)j / 64.0);
}

__global__ void rope_qk()
{
    int bt   = blockIdx.x;
    int tpos = bt % NT;
    int b    = bt / NT;
    int d    = threadIdx.x;
    int j    = d & 63;

    float invf = g_invf[j];
    float ang = (float)tpos * invf;
    float cv = cosf(ang), sv = sinf(ang);
    float sgn = (d < 64) ? -1.f : 1.f;
    const float* base = g_qkv + (size_t)bt * (3 * NC);
    const float scale = 0.088388347648318447f;

#pragma unroll
    for (int h = 0; h < NH; h++) {
        float qv = base[h * ND + d];
        float qp = base[h * ND + (d ^ 64)];
        float kv = base[NC + h * ND + d];
        float kp = base[NC + h * ND + (d ^ 64)];
        float qo = (qv * cv + sgn * qp * sv) * scale;
        float ko = kv * cv + sgn * kp * sv;
        size_t oi = ((size_t)(b * NH + h) * NT + tpos) * ND + d;
        g_qh[oi] = __float2half_rn(qo);
        g_kh[oi] = __float2half_rn(ko);
    }
}

// V transpose: g_qkv v-part [bt][h*128+d] -> g_vth [bh][d][t] (fp16)
__global__ void vt_split()
{
    __shared__ float tile[64][132];
    int t0 = blockIdx.x * 64;
    int h  = blockIdx.y;
    int b  = blockIdx.z;
    int t  = threadIdx.x;

#pragma unroll
    for (int i = 0; i < 8; i++) {
        int id = t + 256 * i;
        int r = id >> 5, c4 = (id & 31) * 4;
        float4 v = *(const float4*)&g_qkv[(size_t)(b * NT + t0 + r) * (3 * NC) + 2 * NC + h * ND + c4];
        *(float4*)&tile[r][c4] = v;
    }
    __syncthreads();

    int d = t >> 1, j0 = (t & 1) * 32;
    size_t out = ((size_t)(b * NH + h) * ND + d) * NT + t0 + j0;
#pragma unroll
    for (int jj = 0; jj < 32; jj += 2) {
        store2h(g_vth, out + jj, tile[j0 + jj][d], tile[j0 + jj + 1][d]);
    }
}

// ---------------------------------------------------------------------------
// Sliding-window flash attention, plain fp16 operands, fp32 softmax/accum.
// CTA: 128 queries; 8 warps = 16 rows x all keys; Q smem-resident (32KB);
// 2-stage K/V pipeline (32KB/stage); warp-level tile skipping.
// ---------------------------------------------------------------------------
#define AQ 128
#define AK 64
#define ASTG 32768
#define ATT_SMEM (32768 + 2 * ASTG)

__global__ __launch_bounds__(256, 1) void swa_mma()
{
    extern __shared__ __align__(1024) char smem[];
    const uint32_t sb = smem_u32(smem);
    const int t = threadIdx.x, wid = t >> 5, lane = t & 31;
    const int q0 = blockIdx.x * AQ;
    const int h = blockIdx.y, b = blockIdx.z;
    const int bh = b * NH + h;
    const size_t hoff = (size_t)bh * NT;

    const uint32_t QH = sb;

    {
        const char* gq = (const char*)(g_qh + (hoff + q0) * ND);
#pragma unroll
        for (int i = 0; i < 8; i++) {
            int id = t + 256 * i;
            int r = id >> 4, u = id & 15;
            CP_ASYNC16(QH + q_off(r, u), gq + (size_t)r * 256 + u * 16);
        }
        CP_COMMIT();
    }

    auto stage_load = [&](int buf, int kt) {
        uint32_t S = sb + 32768 + buf * ASTG;
        const char* gk = (const char*)(g_kh + (hoff + kt) * ND);
#pragma unroll
        for (int i = 0; i < 4; i++) {
            int id = t + 256 * i;
            int r = id >> 4, u = id & 15;
            CP_ASYNC16(S + q_off(r, u), gk + (size_t)r * 256 + u * 16);
        }
#pragma unroll
        for (int i = 0; i < 4; i++) {
            int id = t + 256 * i;
            int r = id >> 3, u = id & 7;
            size_t gb = ((size_t)(bh * ND + r) * NT + kt + u * 8) * 2;
            CP_ASYNC16(S + 16384 + vt_off(r, u), (const char*)g_vth + gb);
        }
        CP_COMMIT();
    };

    int kt0 = q0 - NW; if (kt0 < 0) kt0 = 0;
    const int nt = (q0 + AQ - kt0) / AK;

    stage_load(0, kt0);

    float ov[16][4];
#pragma unroll
    for (int jj = 0; jj < 16; jj++)
#pragma unroll
        for (int e = 0; e < 4; e++) ov[jj][e] = 0.f;
    float mrow0 = -1e30f, mrow1 = -1e30f, lrow0 = 0.f, lrow1 = 0.f;

    const int wrow = wid * 16;
    const int a_row = (lane & 7) + ((lane >> 3) & 1) * 8;
    const int a_ku  = lane >> 4;
    const int b_row = (lane & 7) + ((lane >> 4) & 1) * 8;
    const int b_ku  = (lane >> 3) & 1;
    const int r0g = q0 + wrow + (lane >> 2);

    for (int tt = 0; tt < nt; tt++) {
        const int kt = kt0 + tt * AK;
        if (tt + 1 < nt) { stage_load((tt + 1) & 1, kt + AK); CP_WAIT1(); }
        else             { CP_WAIT0(); }
        __syncthreads();
        const uint32_t S = sb + 32768 + (tt & 1) * ASTG;

        const bool active = (kt <= q0 + wrow + 15) && (kt + AK - 1 >= q0 + wrow - NW);
        if (active) {

        // ---- S = Q.K ----
        float sc[8][4];
#pragma unroll
        for (int f = 0; f < 8; f++)
#pragma unroll
            for (int e = 0; e < 4; e++) sc[f][e] = 0.f;

#pragma unroll
        for (int ku = 0; ku < 8; ku++) {
            uint32_t qh[4];
            LDSM4A(qh, QH + q_off(wrow + a_row, 2 * ku + a_ku));
#pragma unroll
            for (int nj = 0; nj < 4; nj++) {
                uint32_t kh[4];
                LDSM4A(kh, S + q_off(nj * 16 + b_row, 2 * ku + b_ku));
                MMA16816H(sc[nj * 2],     qh[0], qh[1], qh[2], qh[3], kh[0], kh[1]);
                MMA16816H(sc[nj * 2 + 1], qh[0], qh[1], qh[2], qh[3], kh[2], kh[3]);
            }
        }

        const bool cmask = (kt + AK - 1 > q0 + wrow);
        const bool wmask = (kt < q0 + wrow + 15 - NW);
        if (cmask || wmask) {
#pragma unroll
            for (int f = 0; f < 8; f++) {
                int jb = kt + f * 8 + (lane & 3) * 2;
#pragma unroll
                for (int e = 0; e < 2; e++) {
                    int jg = jb + e;
                    if (jg > r0g || jg < r0g - NW)             sc[f][e]     = -1e30f;
                    if (jg > r0g + 8 || jg < r0g + 8 - NW)     sc[f][e + 2] = -1e30f;
                }
            }
        }

        float mt0 = -1e30f, mt1 = -1e30f;
#pragma unroll
        for (int f = 0; f < 8; f++) {
            mt0 = fmaxf(mt0, fmaxf(sc[f][0], sc[f][1]));
            mt1 = fmaxf(mt1, fmaxf(sc[f][2], sc[f][3]));
        }
        mt0 = fmaxf(mt0, __shfl_xor_sync(0xffffffffu, mt0, 1));
        mt0 = fmaxf(mt0, __shfl_xor_sync(0xffffffffu, mt0, 2));
        mt1 = fmaxf(mt1, __shfl_xor_sync(0xffffffffu, mt1, 1));
        mt1 = fmaxf(mt1, __shfl_xor_sync(0xffffffffu, mt1, 2));

        float mn0 = fmaxf(mrow0, mt0), mn1 = fmaxf(mrow1, mt1);
        float al0 = __expf(mrow0 - mn0), al1 = __expf(mrow1 - mn1);
        mrow0 = mn0; mrow1 = mn1;

        float rs0 = 0.f, rs1 = 0.f;
#pragma unroll
        for (int f = 0; f < 8; f++) {
            sc[f][0] = __expf(sc[f][0] - mn0);
            sc[f][1] = __expf(sc[f][1] - mn0);
            sc[f][2] = __expf(sc[f][2] - mn1);
            sc[f][3] = __expf(sc[f][3] - mn1);
            rs0 += sc[f][0] + sc[f][1];
            rs1 += sc[f][2] + sc[f][3];
        }
        rs0 += __shfl_xor_sync(0xffffffffu, rs0, 1);
        rs0 += __shfl_xor_sync(0xffffffffu, rs0, 2);
        rs1 += __shfl_xor_sync(0xffffffffu, rs1, 1);
        rs1 += __shfl_xor_sync(0xffffffffu, rs1, 2);
        lrow0 = lrow0 * al0 + rs0;
        lrow1 = lrow1 * al1 + rs1;

#pragma unroll
        for (int jj = 0; jj < 16; jj++) {
            ov[jj][0] *= al0; ov[jj][1] *= al0;
            ov[jj][2] *= al1; ov[jj][3] *= al1;
        }

        // ---- O += P.V ----
#pragma unroll
        for (int ks = 0; ks < 4; ks++) {
            uint32_t p0 = packh2(sc[2 * ks][0],     sc[2 * ks][1]);
            uint32_t p1 = packh2(sc[2 * ks][2],     sc[2 * ks][3]);
            uint32_t p2 = packh2(sc[2 * ks + 1][0], sc[2 * ks + 1][1]);
            uint32_t p3 = packh2(sc[2 * ks + 1][2], sc[2 * ks + 1][3]);
#pragma unroll
            for (int nj = 0; nj < 8; nj++) {
                uint32_t vh[4];
                LDSM4A(vh, S + 16384 + vt_off(nj * 16 + b_row, ks * 2 + b_ku));
                MMA16816H(ov[nj * 2],     p0, p1, p2, p3, vh[0], vh[1]);
                MMA16816H(ov[nj * 2 + 1], p0, p1, p2, p3, vh[2], vh[3]);
            }
        }

        }   // active
        __syncthreads();
    }

    // ---- finalize: write fp16 for the out-projection ----
    float i0 = 1.f / lrow0, i1 = 1.f / lrow1;
    size_t row0 = (size_t)(b * NT + r0g) * NC;
    size_t row1 = row0 + 8 * NC;
#pragma unroll
    for (int jj = 0; jj < 16; jj++) {
        int c = h * ND + jj * 8 + (lane & 3) * 2;
        store2h(g_ah, row0 + c, ov[jj][0] * i0, ov[jj][1] * i0);
        store2h(g_ah, row1 + c, ov[jj][2] * i1, ov[jj][3] * i1);
    }
}

// ---------------------------------------------------------------------------
extern "C" void kernel_launch(void* const* d_in, const int* in_sizes, int n_in,
                              void* d_out, int out_size)
{
    const float* x     = (const float*)d_in[0];
    const float* w_qkv = (const float*)d_in[1];
    const float* w_o   = (const float*)d_in[2];
    float* out = (float*)d_out;

    float* qkv_ptr;
    cudaGetSymbolAddress((void**)&qkv_ptr, g_qkv);
    __half *xh, *wqh, *woh, *ah;
    cudaGetSymbolAddress((void**)&xh, g_xh);
    cudaGetSymbolAddress((void**)&wqh, g_wqh);
    cudaGetSymbolAddress((void**)&woh, g_woh);
    cudaGetSymbolAddress((void**)&ah, g_ah);

    cudaFuncSetAttribute(gemm_mma, cudaFuncAttributeMaxDynamicSharedMemorySize, GSMEM);
    cudaFuncSetAttribute(swa_mma, cudaFuncAttributeMaxDynamicSharedMemorySize, ATT_SMEM);

    const int M = NB * NT;

    rope_tab<<<1, 64>>>();
    conv_round_h<<<M * NC / 1024, 256>>>(x, xh, M * NC);
    conv_round_h<<<3 * NC * NC / 1024, 256>>>(w_qkv, wqh, 3 * NC * NC);
    conv_round_h<<<NC * NC / 1024, 256>>>(w_o, woh, NC * NC);

    // 1) QKV projection (fp16)
    gemm_mma<<<dim3(3 * NC / 128, M / 128), 256, GSMEM>>>(xh, wqh, qkv_ptr,
                                                          M, 3 * NC, NC);
    // 2) RoPE + V transpose (fp16)
    rope_qk<<<M, ND>>>();
    vt_split<<<dim3(NT / 64, NH, NB), 256>>>();

    // 3) Sliding-window attention (fp16)
    swa_mma<<<dim3(NT / AQ, NH, NB), 256, ATT_SMEM>>>();

    // 4) Output projection (fp16)
    gemm_mma<<<dim3(NC / 128, M / 128), 256, GSMEM>>>(ah, woh, out,
                                                      M, NC, NC);
}